// round 16
// baseline (speedup 1.0000x reference)
#include <cuda_runtime.h>
#include <cuda_bf16.h>
#include <math.h>
#include <stdint.h>

#define BATCH   4
#define SEQ     2048
#define EMBED   512
#define HIDDEN  2048
#define HEADS   8
#define DHEAD   64
#define M_TOK   (BATCH * SEQ)     // 8192
#define QKV_W3  (3 * EMBED)       // 1536
#define NBH     (BATCH * HEADS)   // 32

// ---------------- scratch (device globals; no allocations allowed) ----------
__device__ float g_x1  [M_TOK * EMBED];
// packed bf16x2 hi/lo activations (k-pairs along K dim, row-major [m][K/2])
__device__ uint32_t g_lnh [M_TOK * 256],  g_lnl [M_TOK * 256];
__device__ uint32_t g_atth[M_TOK * 256],  g_attl[M_TOK * 256];
__device__ uint32_t g_f1h [M_TOK * 1024], g_f1l [M_TOK * 1024];
// interleaved {hi,lo} u64 attention operands
__device__ uint2 g_q64[NBH * 32 * SEQ];   // [bh][d2][q]  (pre-scaled by 0.125)
__device__ uint2 g_k64[NBH * 32 * SEQ];   // [bh][d2][k]
__device__ uint2 g_v64[NBH * 1024 * 64];  // [bh][kp][d]
// pre-split packed weights: [K/2][N] as bf16x2 (k-pair per u32)
__device__ uint32_t g_wqkv_h[256 * QKV_W3],  g_wqkv_l[256 * QKV_W3];
__device__ uint32_t g_wproj_h[256 * EMBED],  g_wproj_l[256 * EMBED];
__device__ uint32_t g_wfc1_h [256 * HIDDEN], g_wfc1_l [256 * HIDDEN];
__device__ uint32_t g_wfc2_h [1024 * EMBED], g_wfc2_l [1024 * EMBED];

// ---------------- helpers ----------------------------------------------------
__device__ __forceinline__ void split2(float x0, float x1, uint32_t& hi, uint32_t& lo) {
    __nv_bfloat16 h0 = __float2bfloat16(x0);
    __nv_bfloat16 h1 = __float2bfloat16(x1);
    float r0 = x0 - __bfloat162float(h0);
    float r1 = x1 - __bfloat162float(h1);
    __nv_bfloat162 hp; hp.x = h0; hp.y = h1;
    __nv_bfloat162 lp; lp.x = __float2bfloat16(r0); lp.y = __float2bfloat16(r1);
    hi = *reinterpret_cast<uint32_t*>(&hp);
    lo = *reinterpret_cast<uint32_t*>(&lp);
}

__device__ __forceinline__ void mma_bf16(float* c, const uint32_t* a,
                                         uint32_t b0, uint32_t b1) {
    asm volatile(
        "mma.sync.aligned.m16n8k16.row.col.f32.bf16.bf16.f32 "
        "{%0,%1,%2,%3}, {%4,%5,%6,%7}, {%8,%9}, {%0,%1,%2,%3};"
        : "+f"(c[0]), "+f"(c[1]), "+f"(c[2]), "+f"(c[3])
        : "r"(a[0]), "r"(a[1]), "r"(a[2]), "r"(a[3]), "r"(b0), "r"(b1));
}

__device__ __forceinline__ void cpa16(uint32_t dst, const void* src) {
    asm volatile("cp.async.cg.shared.global [%0], [%1], 16;"
                 :: "r"(dst), "l"(src) : "memory");
}
__device__ __forceinline__ void cpa_commit() {
    asm volatile("cp.async.commit_group;" ::: "memory");
}
__device__ __forceinline__ void cpa_wait0() {
    asm volatile("cp.async.wait_group 0;" ::: "memory");
}

__device__ __forceinline__ float gelu_exact(float v) {
    return 0.5f * v * (1.f + erff(v * 0.70710678118654752f));
}

// ---------------- LayerNorm: one warp per row; packed hi/lo output ----------
__global__ void ln_kernel(const float* __restrict__ x,
                          const float* __restrict__ gamma,
                          const float* __restrict__ beta,
                          uint32_t* __restrict__ oh, uint32_t* __restrict__ ol) {
    int warp = (blockIdx.x * blockDim.x + threadIdx.x) >> 5;
    int lane = threadIdx.x & 31;
    if (warp >= M_TOK) return;
    const float4* xr = (const float4*)(x + (size_t)warp * EMBED);
    float4 v[4];
    float sum = 0.f, sq = 0.f;
#pragma unroll
    for (int i = 0; i < 4; i++) {
        v[i] = xr[lane + 32 * i];
        sum += v[i].x + v[i].y + v[i].z + v[i].w;
        sq  += v[i].x * v[i].x + v[i].y * v[i].y + v[i].z * v[i].z + v[i].w * v[i].w;
    }
#pragma unroll
    for (int o = 16; o; o >>= 1) {
        sum += __shfl_xor_sync(0xffffffffu, sum, o);
        sq  += __shfl_xor_sync(0xffffffffu, sq,  o);
    }
    float mean = sum * (1.f / EMBED);
    float var  = sq * (1.f / EMBED) - mean * mean;
    float rstd = rsqrtf(var + 1e-5f);
    const float4* gg = (const float4*)gamma;
    const float4* bb = (const float4*)beta;
    uint2* ohp = (uint2*)(oh + (size_t)warp * 256);
    uint2* olp = (uint2*)(ol + (size_t)warp * 256);
#pragma unroll
    for (int i = 0; i < 4; i++) {
        float4 gv = gg[lane + 32 * i];
        float4 bv = bb[lane + 32 * i];
        float rx = (v[i].x - mean) * rstd * gv.x + bv.x;
        float ry = (v[i].y - mean) * rstd * gv.y + bv.y;
        float rz = (v[i].z - mean) * rstd * gv.z + bv.z;
        float rw = (v[i].w - mean) * rstd * gv.w + bv.w;
        uint32_t h0, l0, h1, l1;
        split2(rx, ry, h0, l0);
        split2(rz, rw, h1, l1);
        uint2 hv; hv.x = h0; hv.y = h1;
        uint2 lv; lv.x = l0; lv.y = l1;
        ohp[lane + 32 * i] = hv;
        olp[lane + 32 * i] = lv;
    }
}

// ---------------- weight pre-split (all 4 weights, one launch) ---------------
__global__ __launch_bounds__(256)
void wsplit_all(const float* __restrict__ qkv_w, const float* __restrict__ proj_w,
                const float* __restrict__ fc1_w, const float* __restrict__ fc2_w,
                uint32_t* __restrict__ wqh, uint32_t* __restrict__ wql,
                uint32_t* __restrict__ wph, uint32_t* __restrict__ wpl,
                uint32_t* __restrict__ w1h, uint32_t* __restrict__ w1l,
                uint32_t* __restrict__ w2h, uint32_t* __restrict__ w2l) {
    int i = blockIdx.x * 256 + threadIdx.x;   // uint4 work items
    const float* W; uint32_t* Wh; uint32_t* Wl; int N;
    if (i < 98304)       { W = qkv_w;  Wh = wqh; Wl = wql; N = QKV_W3; }
    else if (i < 131072) { i -= 98304;  W = proj_w; Wh = wph; Wl = wpl; N = EMBED; }
    else if (i < 262144) { i -= 131072; W = fc1_w;  Wh = w1h; Wl = w1l; N = HIDDEN; }
    else                 { i -= 262144; W = fc2_w;  Wh = w2h; Wl = w2l; N = EMBED; }
    int nq = N >> 2;
    int k2 = i / nq;
    int n4 = (i - k2 * nq) << 2;
    const float* p0 = W + (size_t)(2 * k2) * N + n4;
    float4 r0 = *(const float4*)p0;
    float4 r1 = *(const float4*)(p0 + N);
    float e0[4] = {r0.x, r0.y, r0.z, r0.w};
    float e1[4] = {r1.x, r1.y, r1.z, r1.w};
    uint32_t hi[4], lo[4];
#pragma unroll
    for (int e = 0; e < 4; e++) split2(e0[e], e1[e], hi[e], lo[e]);
    *(uint4*)&Wh[(size_t)k2 * N + n4] = *(uint4*)hi;
    *(uint4*)&Wl[(size_t)k2 * N + n4] = *(uint4*)lo;
}

// ---------------- bf16 3x-split tensor-core GEMM (all operands pre-split) ----
// EPI: 1 = bias+res->fp32, 2 = bias+GELU->packed hi/lo,
//      3 = bias -> interleaved u64 Q/K/V attention layouts (QKV projection)
#define GST 136
#define AST 12   // A smem row stride in u32 (conflict-free, 16B-aligned)

template<int EPI>
__global__ __launch_bounds__(256, 2)
void bgemm_kernel(const uint32_t* __restrict__ Ahg, const uint32_t* __restrict__ Alg,
                  const uint32_t* __restrict__ Bhg, const uint32_t* __restrict__ Blg,
                  const float* __restrict__ bias, const float* __restrict__ res,
                  float* __restrict__ C, uint32_t* __restrict__ Ch,
                  uint32_t* __restrict__ Cl,
                  uint2* __restrict__ q64, uint2* __restrict__ k64,
                  uint2* __restrict__ v64,
                  int M, int N, int K) {
    __shared__ __align__(16) uint32_t Ah[2][128][AST], Al[2][128][AST];
    __shared__ __align__(16) uint32_t Bh[2][8][GST],  Bl[2][8][GST];

    const int t    = threadIdx.x;
    const int bm   = blockIdx.y * 128;
    const int bn   = blockIdx.x * 128;
    const int w    = t >> 5;
    const int lane = t & 31;
    const int wm   = (w & 3) * 32;
    const int wn   = (w >> 2) * 64;
    const int g    = lane >> 2;
    const int c    = lane & 3;
    const int K2   = K >> 1;

    float acc[2][8][4];
#pragma unroll
    for (int i = 0; i < 2; i++)
#pragma unroll
        for (int j = 0; j < 8; j++)
#pragma unroll
            for (int q = 0; q < 4; q++) acc[i][j][q] = 0.f;

    const int a_row = t >> 1;
    const int a_k2q = (t & 1) * 4;
    const int b_kp  = t >> 5;
    const int b_n4  = (t & 31) * 4;
    const uint32_t* ah_src = Ahg + (size_t)(bm + a_row) * K2 + a_k2q;
    const uint32_t* al_src = Alg + (size_t)(bm + a_row) * K2 + a_k2q;
    const uint32_t* bh_src = Bhg + (size_t)b_kp * N + bn + b_n4;
    const uint32_t* bl_src = Blg + (size_t)b_kp * N + bn + b_n4;
    const int nk = K >> 4;

    const uint32_t ah_dst = (uint32_t)__cvta_generic_to_shared(&Ah[0][a_row][a_k2q]);
    const uint32_t al_dst = (uint32_t)__cvta_generic_to_shared(&Al[0][a_row][a_k2q]);
    const uint32_t bh_dst = (uint32_t)__cvta_generic_to_shared(&Bh[0][b_kp][b_n4]);
    const uint32_t bl_dst = (uint32_t)__cvta_generic_to_shared(&Bl[0][b_kp][b_n4]);
    const uint32_t asb = 128 * AST * 4;   // A buffer stride (bytes)
    const uint32_t bsb = 8 * GST * 4;     // B buffer stride (bytes)

    // prologue: tile 0
    cpa16(ah_dst, ah_src);
    cpa16(al_dst, al_src);
    cpa16(bh_dst, bh_src);
    cpa16(bl_dst, bl_src);
    cpa_commit();
    cpa_wait0();
    __syncthreads();

    for (int kt = 0; kt < nk; kt++) {
        const int buf = kt & 1;
        if (kt + 1 < nk) {
            const uint32_t bo = (buf ^ 1);
            cpa16(ah_dst + bo * asb, ah_src + (kt + 1) * 8);
            cpa16(al_dst + bo * asb, al_src + (kt + 1) * 8);
            cpa16(bh_dst + bo * bsb, bh_src + (size_t)(kt + 1) * 8 * N);
            cpa16(bl_dst + bo * bsb, bl_src + (size_t)(kt + 1) * 8 * N);
            cpa_commit();
        }

        uint32_t ah[2][4], al[2][4];
#pragma unroll
        for (int i = 0; i < 2; i++) {
            const int m0 = wm + 16 * i;
            ah[i][0] = Ah[buf][m0 + g][c];     ah[i][1] = Ah[buf][m0 + g + 8][c];
            ah[i][2] = Ah[buf][m0 + g][c + 4]; ah[i][3] = Ah[buf][m0 + g + 8][c + 4];
            al[i][0] = Al[buf][m0 + g][c];     al[i][1] = Al[buf][m0 + g + 8][c];
            al[i][2] = Al[buf][m0 + g][c + 4]; al[i][3] = Al[buf][m0 + g + 8][c + 4];
        }
#pragma unroll
        for (int j = 0; j < 8; j++) {
            const int n = wn + 8 * j + g;
            uint32_t b0h = Bh[buf][c][n], b1h = Bh[buf][c + 4][n];
            uint32_t b0l = Bl[buf][c][n], b1l = Bl[buf][c + 4][n];
#pragma unroll
            for (int i = 0; i < 2; i++) {
                mma_bf16(acc[i][j], al[i], b0h, b1h);
                mma_bf16(acc[i][j], ah[i], b0l, b1l);
                mma_bf16(acc[i][j], ah[i], b0h, b1h);
            }
        }

        cpa_wait0();
        __syncthreads();
    }

    // epilogue
#pragma unroll
    for (int i = 0; i < 2; i++) {
        const int r0 = bm + wm + 16 * i + g;
#pragma unroll
        for (int j = 0; j < 8; j++) {
            const int n = bn + wn + 8 * j + 2 * c;
            float bx = bias[n], by = bias[n + 1];
#pragma unroll
            for (int half = 0; half < 2; half++) {
                const int row = r0 + 8 * half;
                float v0 = acc[i][j][2 * half + 0] + bx;
                float v1 = acc[i][j][2 * half + 1] + by;
                if (EPI == 2) {
                    v0 = gelu_exact(v0); v1 = gelu_exact(v1);
                    uint32_t hi, lo;
                    split2(v0, v1, hi, lo);
                    size_t off = (size_t)row * (N >> 1) + (n >> 1);
                    Ch[off] = hi; Cl[off] = lo;
                } else if (EPI == 3) {
                    // emit interleaved u64 attention operands directly
                    const int region = n >> 9;        // 0=Q, 1=K, 2=V (warp-uniform)
                    const int nloc = n & 511;
                    const int hh = nloc >> 6;
                    const int d  = nloc & 63;
                    const int tok = row & (SEQ - 1);
                    const int bhI = (row >> 11) * HEADS + hh;
                    if (region < 2) {
                        const float sc = (region == 0) ? 0.125f : 1.f;
                        uint32_t hi, lo;
                        split2(v0 * sc, v1 * sc, hi, lo);
                        size_t off = ((size_t)bhI * 32 + (d >> 1)) * SEQ + tok;
                        uint2 pv; pv.x = hi; pv.y = lo;
                        if (region == 0) q64[off] = pv;
                        else             k64[off] = pv;
                    } else {
                        // pair adjacent tokens (lanes g, g^1) for V layout [kp][d]
                        float p0 = __shfl_xor_sync(0xffffffffu, v0, 4);
                        float p1 = __shfl_xor_sync(0xffffffffu, v1, 4);
                        if ((g & 1) == 0) {
                            size_t off = ((size_t)bhI * 1024 + (tok >> 1)) * 64 + d;
                            uint32_t h0, l0, h1, l1;
                            split2(v0, p0, h0, l0);
                            split2(v1, p1, h1, l1);
                            uint4 pk; pk.x = h0; pk.y = l0; pk.z = h1; pk.w = l1;
                            *(uint4*)&v64[off] = pk;   // off is even -> 16B aligned
                        }
                    }
                } else {
                    if (EPI == 1) {
                        const float2 rv = *(const float2*)(res + (size_t)row * N + n);
                        v0 += rv.x; v1 += rv.y;
                    }
                    float2 o; o.x = v0; o.y = v1;
                    *(float2*)(C + (size_t)row * N + n) = o;
                }
            }
        }
    }
}

// ---------------- tensor-core flash attention (u64 interleaved operands) -----
// 128-key chunks, 1 CTA/SM. All smem offsets in u64 units.
// Q at 0 (32 rows, stride 132); buffers at 4224 + buf*8576:
//   K (32 rows x 128, stride 132) at +0, V (64 rows x 64, stride 68) at +4224.
#define Q64OFF 0
#define BUF0   4224
#define BUFSTR 8576
#define VOFF   4224
#define ATT_U64 (BUF0 + 2 * BUFSTR)        // 21376
#define ASM_BYTES (ATT_U64 * 8)            // 171008

__global__ __launch_bounds__(256, 1)
void attn2_kernel(const uint2* __restrict__ q64, const uint2* __restrict__ k64,
                  const uint2* __restrict__ v64,
                  uint32_t* __restrict__ oh, uint32_t* __restrict__ ol) {
    extern __shared__ __align__(16) uint2 sm2[];
    const uint32_t smb = (uint32_t)__cvta_generic_to_shared(sm2);

    const int t    = threadIdx.x;
    const int w    = t >> 5;
    const int lane = t & 31;
    const int g    = lane >> 2;
    const int c    = lane & 3;
    const int bh   = blockIdx.y;
    const int b    = bh >> 3;
    const int h    = bh & 7;
    const int q0g  = blockIdx.x * 128;
    const int qw   = w * 16;

    // ---- prologue: Q + chunk0 ----
#pragma unroll
    for (int r = 0; r < 8; r++) {
        int idx = t + 256 * r;
        int row = idx >> 6;
        int c2  = (idx & 63) << 1;
        cpa16(smb + (uint32_t)(Q64OFF + row * 132 + c2) * 8,
              &q64[((size_t)bh * 32 + row) * SEQ + q0g + c2]);
    }
#pragma unroll
    for (int r = 0; r < 8; r++) {
        int idx = t + 256 * r;
        int row = idx >> 6;
        int c2  = (idx & 63) << 1;
        cpa16(smb + (uint32_t)(BUF0 + row * 132 + c2) * 8,
              &k64[((size_t)bh * 32 + row) * SEQ + c2]);
    }
#pragma unroll
    for (int r = 0; r < 8; r++) {
        int idx = t + 256 * r;
        int row = idx >> 5;
        int c2  = (idx & 31) << 1;
        cpa16(smb + (uint32_t)(BUF0 + VOFF + row * 68 + c2) * 8,
              &v64[((size_t)bh * 1024 + row) * 64 + c2]);
    }
    cpa_commit();
    cpa_wait0();
    __syncthreads();

    // ---- hoist Q fragments (loop-invariant) ----
    uint32_t qfh[4][4], qfl[4][4];
#pragma unroll
    for (int kb = 0; kb < 4; kb++) {
        const int ra = (8 * kb + c) * 132;
        const int rb = ra + 528;
        uint2 a0 = sm2[ra + qw + g];
        uint2 a1 = sm2[ra + qw + g + 8];
        uint2 a2 = sm2[rb + qw + g];
        uint2 a3 = sm2[rb + qw + g + 8];
        qfh[kb][0] = a0.x; qfh[kb][1] = a1.x; qfh[kb][2] = a2.x; qfh[kb][3] = a3.x;
        qfl[kb][0] = a0.y; qfl[kb][1] = a1.y; qfl[kb][2] = a2.y; qfl[kb][3] = a3.y;
    }

    float oacc[8][4];
#pragma unroll
    for (int j = 0; j < 8; j++)
#pragma unroll
        for (int e = 0; e < 4; e++) oacc[j][e] = 0.f;
    float m0 = -1e30f, m1 = -1e30f, l0 = 0.f, l1 = 0.f;

    for (int ck = 0; ck < 16; ck++) {
        const int buf = ck & 1;
        const uint2* Ks = sm2 + BUF0 + buf * BUFSTR;
        const uint2* Vs = Ks + VOFF;

        // prefetch next chunk into other buffer
        if (ck + 1 < 16) {
            const int k0n = (ck + 1) * 128;
            const uint32_t nb = BUF0 + (buf ^ 1) * BUFSTR;
#pragma unroll
            for (int r = 0; r < 8; r++) {
                int idx = t + 256 * r;
                int row = idx >> 6;
                int c2  = (idx & 63) << 1;
                cpa16(smb + (nb + (uint32_t)(row * 132 + c2)) * 8,
                      &k64[((size_t)bh * 32 + row) * SEQ + k0n + c2]);
            }
#pragma unroll
            for (int r = 0; r < 8; r++) {
                int idx = t + 256 * r;
                int row = idx >> 5;
                int c2  = (idx & 31) << 1;
                cpa16(smb + (nb + VOFF + (uint32_t)(row * 68 + c2)) * 8,
                      &v64[((size_t)bh * 1024 + (k0n >> 1) + row) * 64 + c2]);
            }
            cpa_commit();
        }

        // ---- S = (Q/8) @ K^T ----
        float sacc[16][4];
#pragma unroll
        for (int j = 0; j < 16; j++)
#pragma unroll
            for (int e = 0; e < 4; e++) sacc[j][e] = 0.f;

#pragma unroll
        for (int kb = 0; kb < 4; kb++) {
            const int ra = (8 * kb + c) * 132;
            const int rb = ra + 528;
#pragma unroll
            for (int j = 0; j < 16; j++) {
                uint2 B0 = Ks[ra + 8 * j + g];
                uint2 B1 = Ks[rb + 8 * j + g];
                mma_bf16(sacc[j], qfl[kb], B0.x, B1.x);
                mma_bf16(sacc[j], qfh[kb], B0.y, B1.y);
                mma_bf16(sacc[j], qfh[kb], B0.x, B1.x);
            }
        }

        // ---- online softmax ----
        float cm0 = m0, cm1 = m1;
#pragma unroll
        for (int j = 0; j < 16; j++) {
            cm0 = fmaxf(cm0, fmaxf(sacc[j][0], sacc[j][1]));
            cm1 = fmaxf(cm1, fmaxf(sacc[j][2], sacc[j][3]));
        }
        cm0 = fmaxf(cm0, __shfl_xor_sync(0xffffffffu, cm0, 1));
        cm0 = fmaxf(cm0, __shfl_xor_sync(0xffffffffu, cm0, 2));
        cm1 = fmaxf(cm1, __shfl_xor_sync(0xffffffffu, cm1, 1));
        cm1 = fmaxf(cm1, __shfl_xor_sync(0xffffffffu, cm1, 2));

        float corr0 = __expf(m0 - cm0);
        float corr1 = __expf(m1 - cm1);
        m0 = cm0; m1 = cm1;
        l0 *= corr0; l1 *= corr1;
#pragma unroll
        for (int j = 0; j < 8; j++) {
            oacc[j][0] *= corr0; oacc[j][1] *= corr0;
            oacc[j][2] *= corr1; oacc[j][3] *= corr1;
        }
        float rs0 = 0.f, rs1 = 0.f;
#pragma unroll
        for (int j = 0; j < 16; j++) {
            float p0 = __expf(sacc[j][0] - m0);
            float p1 = __expf(sacc[j][1] - m0);
            float p2 = __expf(sacc[j][2] - m1);
            float p3 = __expf(sacc[j][3] - m1);
            sacc[j][0] = p0; sacc[j][1] = p1; sacc[j][2] = p2; sacc[j][3] = p3;
            rs0 += p0 + p1; rs1 += p2 + p3;
        }
        rs0 += __shfl_xor_sync(0xffffffffu, rs0, 1);
        rs0 += __shfl_xor_sync(0xffffffffu, rs0, 2);
        rs1 += __shfl_xor_sync(0xffffffffu, rs1, 1);
        rs1 += __shfl_xor_sync(0xffffffffu, rs1, 2);
        l0 += rs0; l1 += rs1;

        // ---- O += P @ V ----
#pragma unroll
        for (int kb = 0; kb < 8; kb++) {
            uint32_t ph[4], pl[4];
            split2(sacc[2 * kb][0],     sacc[2 * kb][1],     ph[0], pl[0]);
            split2(sacc[2 * kb][2],     sacc[2 * kb][3],     ph[1], pl[1]);
            split2(sacc[2 * kb + 1][0], sacc[2 * kb + 1][1], ph[2], pl[2]);
            split2(sacc[2 * kb + 1][2], sacc[2 * kb + 1][3], ph[3], pl[3]);
            const int rv  = (8 * kb + c) * 68;
            const int rv2 = rv + 272;
#pragma unroll
            for (int jd = 0; jd < 8; jd++) {
                uint2 V0 = Vs[rv + 8 * jd + g];
                uint2 V1 = Vs[rv2 + 8 * jd + g];
                mma_bf16(oacc[jd], pl, V0.x, V1.x);
                mma_bf16(oacc[jd], ph, V0.y, V1.y);
                mma_bf16(oacc[jd], ph, V0.x, V1.x);
            }
        }

        cpa_wait0();
        __syncthreads();
    }

    // write out as packed hi/lo (A operand of proj GEMM), layout [m][256]
    float inv0 = 1.f / l0, inv1 = 1.f / l1;
    const int qrow = q0g + qw + g;
    const size_t row0 = (size_t)(b * SEQ + qrow);
    const size_t row1 = row0 + 8;
#pragma unroll
    for (int jd = 0; jd < 8; jd++) {
        const int col = 8 * jd + 2 * c;
        const size_t o0 = row0 * 256 + h * 32 + (col >> 1);
        const size_t o1 = row1 * 256 + h * 32 + (col >> 1);
        uint32_t hi, lo;
        split2(oacc[jd][0] * inv0, oacc[jd][1] * inv0, hi, lo);
        oh[o0] = hi; ol[o0] = lo;
        split2(oacc[jd][2] * inv1, oacc[jd][3] * inv1, hi, lo);
        oh[o1] = hi; ol[o1] = lo;
    }
}

// ---------------- driver -----------------------------------------------------
extern "C" void kernel_launch(void* const* d_in, const int* in_sizes, int n_in,
                              void* d_out, int out_size) {
    const float* x      = (const float*)d_in[0];
    const float* ln1_g  = (const float*)d_in[1];
    const float* ln1_b  = (const float*)d_in[2];
    const float* qkv_w  = (const float*)d_in[3];
    const float* qkv_b  = (const float*)d_in[4];
    const float* proj_w = (const float*)d_in[5];
    const float* proj_b = (const float*)d_in[6];
    const float* ln2_g  = (const float*)d_in[7];
    const float* ln2_b  = (const float*)d_in[8];
    const float* fc1_w  = (const float*)d_in[9];
    const float* fc1_b  = (const float*)d_in[10];
    const float* fc2_w  = (const float*)d_in[11];
    const float* fc2_b  = (const float*)d_in[12];
    float* out = (float*)d_out;

    float *p_x1;
    uint32_t *p_lnh, *p_lnl, *p_atth, *p_attl, *p_f1h, *p_f1l;
    uint2 *p_q64, *p_k64, *p_v64;
    uint32_t *w_qkv_h, *w_qkv_l, *w_proj_h, *w_proj_l;
    uint32_t *w_fc1_h, *w_fc1_l, *w_fc2_h, *w_fc2_l;
    cudaGetSymbolAddress((void**)&p_x1,  g_x1);
    cudaGetSymbolAddress((void**)&p_lnh, g_lnh);
    cudaGetSymbolAddress((void**)&p_lnl, g_lnl);
    cudaGetSymbolAddress((void**)&p_atth, g_atth);
    cudaGetSymbolAddress((void**)&p_attl, g_attl);
    cudaGetSymbolAddress((void**)&p_f1h, g_f1h);
    cudaGetSymbolAddress((void**)&p_f1l, g_f1l);
    cudaGetSymbolAddress((void**)&p_q64, g_q64);
    cudaGetSymbolAddress((void**)&p_k64, g_k64);
    cudaGetSymbolAddress((void**)&p_v64, g_v64);
    cudaGetSymbolAddress((void**)&w_qkv_h, g_wqkv_h);
    cudaGetSymbolAddress((void**)&w_qkv_l, g_wqkv_l);
    cudaGetSymbolAddress((void**)&w_proj_h, g_wproj_h);
    cudaGetSymbolAddress((void**)&w_proj_l, g_wproj_l);
    cudaGetSymbolAddress((void**)&w_fc1_h, g_wfc1_h);
    cudaGetSymbolAddress((void**)&w_fc1_l, g_wfc1_l);
    cudaGetSymbolAddress((void**)&w_fc2_h, g_wfc2_h);
    cudaGetSymbolAddress((void**)&w_fc2_l, g_wfc2_l);

    cudaFuncSetAttribute(attn2_kernel,
                         cudaFuncAttributeMaxDynamicSharedMemorySize, ASM_BYTES);

    // 0) weight pre-split (single launch)
    wsplit_all<<<1536, 256>>>(qkv_w, proj_w, fc1_w, fc2_w,
                              w_qkv_h, w_qkv_l, w_proj_h, w_proj_l,
                              w_fc1_h, w_fc1_l, w_fc2_h, w_fc2_l);
    // 1) LN1 -> packed
    ln_kernel<<<M_TOK / 8, 256>>>(x, ln1_g, ln1_b, p_lnh, p_lnl);
    // 2) QKV GEMM -> interleaved u64 Q/K/V attention layouts (fused pconv)
    bgemm_kernel<3><<<dim3(QKV_W3 / 128, M_TOK / 128), 256>>>(
        p_lnh, p_lnl, w_qkv_h, w_qkv_l, qkv_b, nullptr,
        nullptr, nullptr, nullptr,
        p_q64, p_k64, p_v64, M_TOK, QKV_W3, EMBED);
    // 3) flash attention -> packed
    attn2_kernel<<<dim3(SEQ / 128, NBH), 256, ASM_BYTES>>>(
        p_q64, p_k64, p_v64, p_atth, p_attl);
    // 4) x1 = x + att @ proj_w + proj_b -> fp32
    bgemm_kernel<1><<<dim3(EMBED / 128, M_TOK / 128), 256>>>(
        p_atth, p_attl, w_proj_h, w_proj_l, proj_b, x,
        p_x1, nullptr, nullptr,
        nullptr, nullptr, nullptr, M_TOK, EMBED, EMBED);
    // 5) LN2 -> packed
    ln_kernel<<<M_TOK / 8, 256>>>(p_x1, ln2_g, ln2_b, p_lnh, p_lnl);
    // 6) fc1 = gelu(LN2 @ fc1_w + fc1_b) -> packed
    bgemm_kernel<2><<<dim3(HIDDEN / 128, M_TOK / 128), 256>>>(
        p_lnh, p_lnl, w_fc1_h, w_fc1_l, fc1_b, nullptr,
        nullptr, p_f1h, p_f1l,
        nullptr, nullptr, nullptr, M_TOK, HIDDEN, EMBED);
    // 7) out = x1 + fc1 @ fc2_w + fc2_b -> fp32
    bgemm_kernel<1><<<dim3(EMBED / 128, M_TOK / 128), 256>>>(
        p_f1h, p_f1l, w_fc2_h, w_fc2_l, fc2_b, p_x1,
        out, nullptr, nullptr,
        nullptr, nullptr, nullptr, M_TOK, EMBED, HIDDEN);
}

// round 17
// speedup vs baseline: 1.0366x; 1.0366x over previous
#include <cuda_runtime.h>
#include <cuda_bf16.h>
#include <math.h>
#include <stdint.h>

#define BATCH   4
#define SEQ     2048
#define EMBED   512
#define HIDDEN  2048
#define HEADS   8
#define DHEAD   64
#define M_TOK   (BATCH * SEQ)     // 8192
#define QKV_W3  (3 * EMBED)       // 1536
#define NBH     (BATCH * HEADS)   // 32

// ---------------- scratch (device globals; no allocations allowed) ----------
__device__ float g_x1  [M_TOK * EMBED];
// packed bf16x2 hi/lo activations (k-pairs along K dim, row-major [m][K/2])
__device__ uint32_t g_lnh [M_TOK * 256],  g_lnl [M_TOK * 256];
__device__ uint32_t g_atth[M_TOK * 256],  g_attl[M_TOK * 256];
__device__ uint32_t g_f1h [M_TOK * 1024], g_f1l [M_TOK * 1024];
// packed bf16x2 (hi/lo split) operands for attention
__device__ uint32_t g_qh[NBH * 32 * SEQ];   // [bh][d2][q]  (pre-scaled by 0.125*log2e)
__device__ uint32_t g_ql[NBH * 32 * SEQ];
__device__ uint32_t g_kh[NBH * 32 * SEQ];   // [bh][d2][k]
__device__ uint32_t g_kl[NBH * 32 * SEQ];
__device__ uint32_t g_vh[NBH * 1024 * 64];  // [bh][kp][d]
__device__ uint32_t g_vl[NBH * 1024 * 64];
// pre-split packed weights: [K/2][N] as bf16x2 (k-pair per u32)
__device__ uint32_t g_wqkv_h[256 * QKV_W3],  g_wqkv_l[256 * QKV_W3];
__device__ uint32_t g_wproj_h[256 * EMBED],  g_wproj_l[256 * EMBED];
__device__ uint32_t g_wfc1_h [256 * HIDDEN], g_wfc1_l [256 * HIDDEN];
__device__ uint32_t g_wfc2_h [1024 * EMBED], g_wfc2_l [1024 * EMBED];

// ---------------- helpers ----------------------------------------------------
__device__ __forceinline__ void split2(float x0, float x1, uint32_t& hi, uint32_t& lo) {
    __nv_bfloat16 h0 = __float2bfloat16(x0);
    __nv_bfloat16 h1 = __float2bfloat16(x1);
    float r0 = x0 - __bfloat162float(h0);
    float r1 = x1 - __bfloat162float(h1);
    __nv_bfloat162 hp; hp.x = h0; hp.y = h1;
    __nv_bfloat162 lp; lp.x = __float2bfloat16(r0); lp.y = __float2bfloat16(r1);
    hi = *reinterpret_cast<uint32_t*>(&hp);
    lo = *reinterpret_cast<uint32_t*>(&lp);
}

__device__ __forceinline__ void mma_bf16(float* c, const uint32_t* a,
                                         uint32_t b0, uint32_t b1) {
    asm volatile(
        "mma.sync.aligned.m16n8k16.row.col.f32.bf16.bf16.f32 "
        "{%0,%1,%2,%3}, {%4,%5,%6,%7}, {%8,%9}, {%0,%1,%2,%3};"
        : "+f"(c[0]), "+f"(c[1]), "+f"(c[2]), "+f"(c[3])
        : "r"(a[0]), "r"(a[1]), "r"(a[2]), "r"(a[3]), "r"(b0), "r"(b1));
}

__device__ __forceinline__ void cpa16(uint32_t dst, const void* src) {
    asm volatile("cp.async.cg.shared.global [%0], [%1], 16;"
                 :: "r"(dst), "l"(src) : "memory");
}
__device__ __forceinline__ void cpa_commit() {
    asm volatile("cp.async.commit_group;" ::: "memory");
}
__device__ __forceinline__ void cpa_wait0() {
    asm volatile("cp.async.wait_group 0;" ::: "memory");
}

__device__ __forceinline__ float gelu_exact(float v) {
    return 0.5f * v * (1.f + erff(v * 0.70710678118654752f));
}

// ---------------- LayerNorm: one warp per row; packed hi/lo output ----------
__global__ void ln_kernel(const float* __restrict__ x,
                          const float* __restrict__ gamma,
                          const float* __restrict__ beta,
                          uint32_t* __restrict__ oh, uint32_t* __restrict__ ol) {
    int warp = (blockIdx.x * blockDim.x + threadIdx.x) >> 5;
    int lane = threadIdx.x & 31;
    if (warp >= M_TOK) return;
    const float4* xr = (const float4*)(x + (size_t)warp * EMBED);
    float4 v[4];
    float sum = 0.f, sq = 0.f;
#pragma unroll
    for (int i = 0; i < 4; i++) {
        v[i] = xr[lane + 32 * i];
        sum += v[i].x + v[i].y + v[i].z + v[i].w;
        sq  += v[i].x * v[i].x + v[i].y * v[i].y + v[i].z * v[i].z + v[i].w * v[i].w;
    }
#pragma unroll
    for (int o = 16; o; o >>= 1) {
        sum += __shfl_xor_sync(0xffffffffu, sum, o);
        sq  += __shfl_xor_sync(0xffffffffu, sq,  o);
    }
    float mean = sum * (1.f / EMBED);
    float var  = sq * (1.f / EMBED) - mean * mean;
    float rstd = rsqrtf(var + 1e-5f);
    const float4* gg = (const float4*)gamma;
    const float4* bb = (const float4*)beta;
    uint2* ohp = (uint2*)(oh + (size_t)warp * 256);
    uint2* olp = (uint2*)(ol + (size_t)warp * 256);
#pragma unroll
    for (int i = 0; i < 4; i++) {
        float4 gv = gg[lane + 32 * i];
        float4 bv = bb[lane + 32 * i];
        float rx = (v[i].x - mean) * rstd * gv.x + bv.x;
        float ry = (v[i].y - mean) * rstd * gv.y + bv.y;
        float rz = (v[i].z - mean) * rstd * gv.z + bv.z;
        float rw = (v[i].w - mean) * rstd * gv.w + bv.w;
        uint32_t h0, l0, h1, l1;
        split2(rx, ry, h0, l0);
        split2(rz, rw, h1, l1);
        uint2 hv; hv.x = h0; hv.y = h1;
        uint2 lv; lv.x = l0; lv.y = l1;
        ohp[lane + 32 * i] = hv;
        olp[lane + 32 * i] = lv;
    }
}

// ---------------- weight pre-split (all 4 weights, one launch) ---------------
__global__ __launch_bounds__(256)
void wsplit_all(const float* __restrict__ qkv_w, const float* __restrict__ proj_w,
                const float* __restrict__ fc1_w, const float* __restrict__ fc2_w,
                uint32_t* __restrict__ wqh, uint32_t* __restrict__ wql,
                uint32_t* __restrict__ wph, uint32_t* __restrict__ wpl,
                uint32_t* __restrict__ w1h, uint32_t* __restrict__ w1l,
                uint32_t* __restrict__ w2h, uint32_t* __restrict__ w2l) {
    int i = blockIdx.x * 256 + threadIdx.x;   // uint4 work items
    const float* W; uint32_t* Wh; uint32_t* Wl; int N;
    if (i < 98304)       { W = qkv_w;  Wh = wqh; Wl = wql; N = QKV_W3; }
    else if (i < 131072) { i -= 98304;  W = proj_w; Wh = wph; Wl = wpl; N = EMBED; }
    else if (i < 262144) { i -= 131072; W = fc1_w;  Wh = w1h; Wl = w1l; N = HIDDEN; }
    else                 { i -= 262144; W = fc2_w;  Wh = w2h; Wl = w2l; N = EMBED; }
    int nq = N >> 2;
    int k2 = i / nq;
    int n4 = (i - k2 * nq) << 2;
    const float* p0 = W + (size_t)(2 * k2) * N + n4;
    float4 r0 = *(const float4*)p0;
    float4 r1 = *(const float4*)(p0 + N);
    float e0[4] = {r0.x, r0.y, r0.z, r0.w};
    float e1[4] = {r1.x, r1.y, r1.z, r1.w};
    uint32_t hi[4], lo[4];
#pragma unroll
    for (int e = 0; e < 4; e++) split2(e0[e], e1[e], hi[e], lo[e]);
    *(uint4*)&Wh[(size_t)k2 * N + n4] = *(uint4*)hi;
    *(uint4*)&Wl[(size_t)k2 * N + n4] = *(uint4*)lo;
}

// ---------------- bf16 3x-split tensor-core GEMM (all operands pre-split) ----
// EPI: 1 = bias+res->fp32, 2 = bias+GELU->packed hi/lo,
//      3 = bias -> packed Q/K/V attention layouts (QKV projection)
#define GST 136
#define AST 12   // A smem row stride in u32 (conflict-free, 16B-aligned)

template<int EPI>
__global__ __launch_bounds__(256, 2)
void bgemm_kernel(const uint32_t* __restrict__ Ahg, const uint32_t* __restrict__ Alg,
                  const uint32_t* __restrict__ Bhg, const uint32_t* __restrict__ Blg,
                  const float* __restrict__ bias, const float* __restrict__ res,
                  float* __restrict__ C, uint32_t* __restrict__ Ch,
                  uint32_t* __restrict__ Cl,
                  uint32_t* __restrict__ qh_, uint32_t* __restrict__ ql_,
                  uint32_t* __restrict__ kh_, uint32_t* __restrict__ kl_,
                  uint32_t* __restrict__ vh_, uint32_t* __restrict__ vl_,
                  int M, int N, int K) {
    __shared__ __align__(16) uint32_t Ah[2][128][AST], Al[2][128][AST];
    __shared__ __align__(16) uint32_t Bh[2][8][GST],  Bl[2][8][GST];

    const int t    = threadIdx.x;
    const int bm   = blockIdx.y * 128;
    const int bn   = blockIdx.x * 128;
    const int w    = t >> 5;
    const int lane = t & 31;
    const int wm   = (w & 3) * 32;
    const int wn   = (w >> 2) * 64;
    const int g    = lane >> 2;
    const int c    = lane & 3;
    const int K2   = K >> 1;

    float acc[2][8][4];
#pragma unroll
    for (int i = 0; i < 2; i++)
#pragma unroll
        for (int j = 0; j < 8; j++)
#pragma unroll
            for (int q = 0; q < 4; q++) acc[i][j][q] = 0.f;

    const int a_row = t >> 1;
    const int a_k2q = (t & 1) * 4;
    const int b_kp  = t >> 5;
    const int b_n4  = (t & 31) * 4;
    const uint32_t* ah_src = Ahg + (size_t)(bm + a_row) * K2 + a_k2q;
    const uint32_t* al_src = Alg + (size_t)(bm + a_row) * K2 + a_k2q;
    const uint32_t* bh_src = Bhg + (size_t)b_kp * N + bn + b_n4;
    const uint32_t* bl_src = Blg + (size_t)b_kp * N + bn + b_n4;
    const int nk = K >> 4;

    const uint32_t ah_dst = (uint32_t)__cvta_generic_to_shared(&Ah[0][a_row][a_k2q]);
    const uint32_t al_dst = (uint32_t)__cvta_generic_to_shared(&Al[0][a_row][a_k2q]);
    const uint32_t bh_dst = (uint32_t)__cvta_generic_to_shared(&Bh[0][b_kp][b_n4]);
    const uint32_t bl_dst = (uint32_t)__cvta_generic_to_shared(&Bl[0][b_kp][b_n4]);
    const uint32_t asb = 128 * AST * 4;   // A buffer stride (bytes)
    const uint32_t bsb = 8 * GST * 4;     // B buffer stride (bytes)

    // prologue: tile 0
    cpa16(ah_dst, ah_src);
    cpa16(al_dst, al_src);
    cpa16(bh_dst, bh_src);
    cpa16(bl_dst, bl_src);
    cpa_commit();
    cpa_wait0();
    __syncthreads();

    for (int kt = 0; kt < nk; kt++) {
        const int buf = kt & 1;
        if (kt + 1 < nk) {
            const uint32_t bo = (buf ^ 1);
            cpa16(ah_dst + bo * asb, ah_src + (kt + 1) * 8);
            cpa16(al_dst + bo * asb, al_src + (kt + 1) * 8);
            cpa16(bh_dst + bo * bsb, bh_src + (size_t)(kt + 1) * 8 * N);
            cpa16(bl_dst + bo * bsb, bl_src + (size_t)(kt + 1) * 8 * N);
            cpa_commit();
        }

        uint32_t ah[2][4], al[2][4];
#pragma unroll
        for (int i = 0; i < 2; i++) {
            const int m0 = wm + 16 * i;
            ah[i][0] = Ah[buf][m0 + g][c];     ah[i][1] = Ah[buf][m0 + g + 8][c];
            ah[i][2] = Ah[buf][m0 + g][c + 4]; ah[i][3] = Ah[buf][m0 + g + 8][c + 4];
            al[i][0] = Al[buf][m0 + g][c];     al[i][1] = Al[buf][m0 + g + 8][c];
            al[i][2] = Al[buf][m0 + g][c + 4]; al[i][3] = Al[buf][m0 + g + 8][c + 4];
        }
#pragma unroll
        for (int j = 0; j < 8; j++) {
            const int n = wn + 8 * j + g;
            uint32_t b0h = Bh[buf][c][n], b1h = Bh[buf][c + 4][n];
            uint32_t b0l = Bl[buf][c][n], b1l = Bl[buf][c + 4][n];
#pragma unroll
            for (int i = 0; i < 2; i++) {
                mma_bf16(acc[i][j], al[i], b0h, b1h);
                mma_bf16(acc[i][j], ah[i], b0l, b1l);
                mma_bf16(acc[i][j], ah[i], b0h, b1h);
            }
        }

        cpa_wait0();
        __syncthreads();
    }

    // epilogue
#pragma unroll
    for (int i = 0; i < 2; i++) {
        const int r0 = bm + wm + 16 * i + g;
#pragma unroll
        for (int j = 0; j < 8; j++) {
            const int n = bn + wn + 8 * j + 2 * c;
            float bx = bias[n], by = bias[n + 1];
#pragma unroll
            for (int half = 0; half < 2; half++) {
                const int row = r0 + 8 * half;
                float v0 = acc[i][j][2 * half + 0] + bx;
                float v1 = acc[i][j][2 * half + 1] + by;
                if (EPI == 2) {
                    v0 = gelu_exact(v0); v1 = gelu_exact(v1);
                    uint32_t hi, lo;
                    split2(v0, v1, hi, lo);
                    size_t off = (size_t)row * (N >> 1) + (n >> 1);
                    Ch[off] = hi; Cl[off] = lo;
                } else if (EPI == 3) {
                    // emit packed attention operands directly
                    const int region = n >> 9;        // 0=Q, 1=K, 2=V (warp-uniform)
                    const int nloc = n & 511;
                    const int hh = nloc >> 6;
                    const int d  = nloc & 63;
                    const int tok = row & (SEQ - 1);
                    const int bhI = (row >> 11) * HEADS + hh;
                    if (region < 2) {
                        // Q pre-scaled by 0.125 * log2(e) so softmax uses exp2
                        const float sc = (region == 0) ? 0.18033688011112042f : 1.f;
                        uint32_t hi, lo;
                        split2(v0 * sc, v1 * sc, hi, lo);
                        size_t off = ((size_t)bhI * 32 + (d >> 1)) * SEQ + tok;
                        if (region == 0) { qh_[off] = hi; ql_[off] = lo; }
                        else             { kh_[off] = hi; kl_[off] = lo; }
                    } else {
                        // pair adjacent tokens (lanes g, g^1) for V layout [kp][d]
                        float p0 = __shfl_xor_sync(0xffffffffu, v0, 4);
                        float p1 = __shfl_xor_sync(0xffffffffu, v1, 4);
                        if ((g & 1) == 0) {
                            size_t off = ((size_t)bhI * 1024 + (tok >> 1)) * 64 + d;
                            uint32_t hi, lo;
                            split2(v0, p0, hi, lo);
                            vh_[off] = hi; vl_[off] = lo;
                            split2(v1, p1, hi, lo);
                            vh_[off + 1] = hi; vl_[off + 1] = lo;
                        }
                    }
                } else {
                    if (EPI == 1) {
                        const float2 rv = *(const float2*)(res + (size_t)row * N + n);
                        v0 += rv.x; v1 += rv.y;
                    }
                    float2 o; o.x = v0; o.y = v1;
                    *(float2*)(C + (size_t)row * N + n) = o;
                }
            }
        }
    }
}

// ---------------- tensor-core flash attention (cp.async double-buffered) -----
// 128-key chunks, 1 CTA/SM. Softmax in base-2 log space (Q pre-scaled).
#define AQH 0
#define AQL 4352
#define AKB 8704            // + buf*8704 ; KH +0, KL +4352
#define AVB 26112           // + buf*9216 ; VH +0, VL +4608
#define ASM_U32 44544
#define ASM_BYTES (ASM_U32 * 4)

__global__ __launch_bounds__(256, 1)
void attn2_kernel(const uint32_t* __restrict__ qh, const uint32_t* __restrict__ ql,
                  const uint32_t* __restrict__ kh, const uint32_t* __restrict__ kl,
                  const uint32_t* __restrict__ vh, const uint32_t* __restrict__ vl,
                  uint32_t* __restrict__ oh, uint32_t* __restrict__ ol) {
    extern __shared__ __align__(16) uint32_t sm[];
    const uint32_t smb = (uint32_t)__cvta_generic_to_shared(sm);

    const int t    = threadIdx.x;
    const int w    = t >> 5;
    const int lane = t & 31;
    const int g    = lane >> 2;
    const int c    = lane & 3;
    const int bh   = blockIdx.y;
    const int b    = bh >> 3;
    const int h    = bh & 7;
    const int q0g  = blockIdx.x * 128;
    const int qw   = w * 16;

    const int l_d2 = t >> 5;
    const int l_c4 = (t & 31) << 2;
    const int l_kp = t >> 4;
    const int l_v4 = (t & 15) << 2;

    // prologue: Q + chunk0
#pragma unroll
    for (int r = 0; r < 4; r++) {
        int d2 = l_d2 + 8 * r;
        size_t src = ((size_t)bh * 32 + d2) * SEQ + q0g + l_c4;
        uint32_t doff = (d2 * 136 + l_c4) * 4;
        cpa16(smb + AQH * 4 + doff, &qh[src]);
        cpa16(smb + AQL * 4 + doff, &ql[src]);
    }
#pragma unroll
    for (int r = 0; r < 4; r++) {
        int d2 = l_d2 + 8 * r;
        size_t src = ((size_t)bh * 32 + d2) * SEQ + l_c4;
        uint32_t doff = (d2 * 136 + l_c4) * 4;
        cpa16(smb + AKB * 4 + doff, &kh[src]);
        cpa16(smb + (AKB + 4352) * 4 + doff, &kl[src]);
    }
#pragma unroll
    for (int r = 0; r < 4; r++) {
        int kp = l_kp + 16 * r;
        size_t src = ((size_t)bh * 1024 + kp) * 64 + l_v4;
        uint32_t doff = (kp * 72 + l_v4) * 4;
        cpa16(smb + AVB * 4 + doff, &vh[src]);
        cpa16(smb + (AVB + 4608) * 4 + doff, &vl[src]);
    }
    cpa_commit();
    cpa_wait0();
    __syncthreads();

    const uint32_t* QH = sm + AQH;
    const uint32_t* QL = sm + AQL;
    uint32_t qfh[4][4], qfl[4][4];
#pragma unroll
    for (int kb = 0; kb < 4; kb++) {
        const int ra = (8 * kb + c) * 136;
        const int rb = ra + 4 * 136;
        qfh[kb][0] = QH[ra + qw + g]; qfh[kb][1] = QH[ra + qw + g + 8];
        qfh[kb][2] = QH[rb + qw + g]; qfh[kb][3] = QH[rb + qw + g + 8];
        qfl[kb][0] = QL[ra + qw + g]; qfl[kb][1] = QL[ra + qw + g + 8];
        qfl[kb][2] = QL[rb + qw + g]; qfl[kb][3] = QL[rb + qw + g + 8];
    }

    float oacc[8][4];
#pragma unroll
    for (int j = 0; j < 8; j++)
#pragma unroll
        for (int e = 0; e < 4; e++) oacc[j][e] = 0.f;
    float m0 = -1e30f, m1 = -1e30f, l0 = 0.f, l1 = 0.f;

    for (int ck = 0; ck < 16; ck++) {
        const int buf = ck & 1;
        const uint32_t* KH = sm + AKB + buf * 8704;
        const uint32_t* KL = KH + 4352;
        const uint32_t* VH = sm + AVB + buf * 9216;
        const uint32_t* VL = VH + 4608;

        if (ck + 1 < 16) {
            const int k0n = (ck + 1) * 128;
            const uint32_t kbase = AKB + (buf ^ 1) * 8704;
            const uint32_t vbase = AVB + (buf ^ 1) * 9216;
#pragma unroll
            for (int r = 0; r < 4; r++) {
                int d2 = l_d2 + 8 * r;
                size_t src = ((size_t)bh * 32 + d2) * SEQ + k0n + l_c4;
                uint32_t doff = (d2 * 136 + l_c4) * 4;
                cpa16(smb + kbase * 4 + doff, &kh[src]);
                cpa16(smb + (kbase + 4352) * 4 + doff, &kl[src]);
            }
#pragma unroll
            for (int r = 0; r < 4; r++) {
                int kp = l_kp + 16 * r;
                size_t src = ((size_t)bh * 1024 + (k0n >> 1) + kp) * 64 + l_v4;
                uint32_t doff = (kp * 72 + l_v4) * 4;
                cpa16(smb + vbase * 4 + doff, &vh[src]);
                cpa16(smb + (vbase + 4608) * 4 + doff, &vl[src]);
            }
            cpa_commit();
        }

        // S2 = (Q * 0.125*log2e) @ K^T  (base-2 logits)
        float sacc[16][4];
#pragma unroll
        for (int j = 0; j < 16; j++)
#pragma unroll
            for (int e = 0; e < 4; e++) sacc[j][e] = 0.f;

#pragma unroll
        for (int kb = 0; kb < 4; kb++) {
            const int ra = (8 * kb + c) * 136;
            const int rb = ra + 4 * 136;
#pragma unroll
            for (int j = 0; j < 16; j++) {
                uint32_t b0h = KH[ra + 8 * j + g], b1h = KH[rb + 8 * j + g];
                uint32_t b0l = KL[ra + 8 * j + g], b1l = KL[rb + 8 * j + g];
                mma_bf16(sacc[j], qfl[kb], b0h, b1h);
                mma_bf16(sacc[j], qfh[kb], b0l, b1l);
                mma_bf16(sacc[j], qfh[kb], b0h, b1h);
            }
        }

        // online softmax (base-2)
        float cm0 = m0, cm1 = m1;
#pragma unroll
        for (int j = 0; j < 16; j++) {
            cm0 = fmaxf(cm0, fmaxf(sacc[j][0], sacc[j][1]));
            cm1 = fmaxf(cm1, fmaxf(sacc[j][2], sacc[j][3]));
        }
        cm0 = fmaxf(cm0, __shfl_xor_sync(0xffffffffu, cm0, 1));
        cm0 = fmaxf(cm0, __shfl_xor_sync(0xffffffffu, cm0, 2));
        cm1 = fmaxf(cm1, __shfl_xor_sync(0xffffffffu, cm1, 1));
        cm1 = fmaxf(cm1, __shfl_xor_sync(0xffffffffu, cm1, 2));

        float corr0 = exp2f(m0 - cm0);
        float corr1 = exp2f(m1 - cm1);
        m0 = cm0; m1 = cm1;
        l0 *= corr0; l1 *= corr1;
#pragma unroll
        for (int j = 0; j < 8; j++) {
            oacc[j][0] *= corr0; oacc[j][1] *= corr0;
            oacc[j][2] *= corr1; oacc[j][3] *= corr1;
        }
        float rs0 = 0.f, rs1 = 0.f;
#pragma unroll
        for (int j = 0; j < 16; j++) {
            float p0 = exp2f(sacc[j][0] - m0);
            float p1 = exp2f(sacc[j][1] - m0);
            float p2 = exp2f(sacc[j][2] - m1);
            float p3 = exp2f(sacc[j][3] - m1);
            sacc[j][0] = p0; sacc[j][1] = p1; sacc[j][2] = p2; sacc[j][3] = p3;
            rs0 += p0 + p1; rs1 += p2 + p3;
        }
        rs0 += __shfl_xor_sync(0xffffffffu, rs0, 1);
        rs0 += __shfl_xor_sync(0xffffffffu, rs0, 2);
        rs1 += __shfl_xor_sync(0xffffffffu, rs1, 1);
        rs1 += __shfl_xor_sync(0xffffffffu, rs1, 2);
        l0 += rs0; l1 += rs1;

        // O += P @ V
#pragma unroll
        for (int kb = 0; kb < 8; kb++) {
            uint32_t ph[4], pl[4];
            split2(sacc[2 * kb][0],     sacc[2 * kb][1],     ph[0], pl[0]);
            split2(sacc[2 * kb][2],     sacc[2 * kb][3],     ph[1], pl[1]);
            split2(sacc[2 * kb + 1][0], sacc[2 * kb + 1][1], ph[2], pl[2]);
            split2(sacc[2 * kb + 1][2], sacc[2 * kb + 1][3], ph[3], pl[3]);
            const int rv  = (8 * kb + c) * 72;
            const int rv2 = rv + 4 * 72;
#pragma unroll
            for (int jd = 0; jd < 8; jd++) {
                uint32_t b0h = VH[rv + 8 * jd + g], b1h = VH[rv2 + 8 * jd + g];
                uint32_t b0l = VL[rv + 8 * jd + g], b1l = VL[rv2 + 8 * jd + g];
                mma_bf16(oacc[jd], pl, b0h, b1h);
                mma_bf16(oacc[jd], ph, b0l, b1l);
                mma_bf16(oacc[jd], ph, b0h, b1h);
            }
        }

        cpa_wait0();
        __syncthreads();
    }

    // write out as packed hi/lo (A operand of proj GEMM), layout [m][256]
    float inv0 = 1.f / l0, inv1 = 1.f / l1;
    const int qrow = q0g + qw + g;
    const size_t row0 = (size_t)(b * SEQ + qrow);
    const size_t row1 = row0 + 8;
#pragma unroll
    for (int jd = 0; jd < 8; jd++) {
        const int col = 8 * jd + 2 * c;
        const size_t o0 = row0 * 256 + h * 32 + (col >> 1);
        const size_t o1 = row1 * 256 + h * 32 + (col >> 1);
        uint32_t hi, lo;
        split2(oacc[jd][0] * inv0, oacc[jd][1] * inv0, hi, lo);
        oh[o0] = hi; ol[o0] = lo;
        split2(oacc[jd][2] * inv1, oacc[jd][3] * inv1, hi, lo);
        oh[o1] = hi; ol[o1] = lo;
    }
}

// ---------------- driver -----------------------------------------------------
extern "C" void kernel_launch(void* const* d_in, const int* in_sizes, int n_in,
                              void* d_out, int out_size) {
    const float* x      = (const float*)d_in[0];
    const float* ln1_g  = (const float*)d_in[1];
    const float* ln1_b  = (const float*)d_in[2];
    const float* qkv_w  = (const float*)d_in[3];
    const float* qkv_b  = (const float*)d_in[4];
    const float* proj_w = (const float*)d_in[5];
    const float* proj_b = (const float*)d_in[6];
    const float* ln2_g  = (const float*)d_in[7];
    const float* ln2_b  = (const float*)d_in[8];
    const float* fc1_w  = (const float*)d_in[9];
    const float* fc1_b  = (const float*)d_in[10];
    const float* fc2_w  = (const float*)d_in[11];
    const float* fc2_b  = (const float*)d_in[12];
    float* out = (float*)d_out;

    float *p_x1;
    uint32_t *p_lnh, *p_lnl, *p_atth, *p_attl, *p_f1h, *p_f1l;
    uint32_t *p_qh, *p_ql, *p_kh, *p_kl, *p_vh, *p_vl;
    uint32_t *w_qkv_h, *w_qkv_l, *w_proj_h, *w_proj_l;
    uint32_t *w_fc1_h, *w_fc1_l, *w_fc2_h, *w_fc2_l;
    cudaGetSymbolAddress((void**)&p_x1,  g_x1);
    cudaGetSymbolAddress((void**)&p_lnh, g_lnh);
    cudaGetSymbolAddress((void**)&p_lnl, g_lnl);
    cudaGetSymbolAddress((void**)&p_atth, g_atth);
    cudaGetSymbolAddress((void**)&p_attl, g_attl);
    cudaGetSymbolAddress((void**)&p_f1h, g_f1h);
    cudaGetSymbolAddress((void**)&p_f1l, g_f1l);
    cudaGetSymbolAddress((void**)&p_qh,  g_qh);
    cudaGetSymbolAddress((void**)&p_ql,  g_ql);
    cudaGetSymbolAddress((void**)&p_kh,  g_kh);
    cudaGetSymbolAddress((void**)&p_kl,  g_kl);
    cudaGetSymbolAddress((void**)&p_vh,  g_vh);
    cudaGetSymbolAddress((void**)&p_vl,  g_vl);
    cudaGetSymbolAddress((void**)&w_qkv_h, g_wqkv_h);
    cudaGetSymbolAddress((void**)&w_qkv_l, g_wqkv_l);
    cudaGetSymbolAddress((void**)&w_proj_h, g_wproj_h);
    cudaGetSymbolAddress((void**)&w_proj_l, g_wproj_l);
    cudaGetSymbolAddress((void**)&w_fc1_h, g_wfc1_h);
    cudaGetSymbolAddress((void**)&w_fc1_l, g_wfc1_l);
    cudaGetSymbolAddress((void**)&w_fc2_h, g_wfc2_h);
    cudaGetSymbolAddress((void**)&w_fc2_l, g_wfc2_l);

    cudaFuncSetAttribute(attn2_kernel,
                         cudaFuncAttributeMaxDynamicSharedMemorySize, ASM_BYTES);

    // 0) weight pre-split (single launch)
    wsplit_all<<<1536, 256>>>(qkv_w, proj_w, fc1_w, fc2_w,
                              w_qkv_h, w_qkv_l, w_proj_h, w_proj_l,
                              w_fc1_h, w_fc1_l, w_fc2_h, w_fc2_l);
    // 1) LN1 -> packed
    ln_kernel<<<M_TOK / 8, 256>>>(x, ln1_g, ln1_b, p_lnh, p_lnl);
    // 2) QKV GEMM -> packed Q/K/V attention layouts (fused pconv)
    bgemm_kernel<3><<<dim3(QKV_W3 / 128, M_TOK / 128), 256>>>(
        p_lnh, p_lnl, w_qkv_h, w_qkv_l, qkv_b, nullptr,
        nullptr, nullptr, nullptr,
        p_qh, p_ql, p_kh, p_kl, p_vh, p_vl, M_TOK, QKV_W3, EMBED);
    // 3) flash attention -> packed
    attn2_kernel<<<dim3(SEQ / 128, NBH), 256, ASM_BYTES>>>(
        p_qh, p_ql, p_kh, p_kl, p_vh, p_vl, p_atth, p_attl);
    // 4) x1 = x + att @ proj_w + proj_b -> fp32
    bgemm_kernel<1><<<dim3(EMBED / 128, M_TOK / 128), 256>>>(
        p_atth, p_attl, w_proj_h, w_proj_l, proj_b, x,
        p_x1, nullptr, nullptr,
        nullptr, nullptr, nullptr, nullptr, nullptr, nullptr, M_TOK, EMBED, EMBED);
    // 5) LN2 -> packed
    ln_kernel<<<M_TOK / 8, 256>>>(p_x1, ln2_g, ln2_b, p_lnh, p_lnl);
    // 6) fc1 = gelu(LN2 @ fc1_w + fc1_b) -> packed
    bgemm_kernel<2><<<dim3(HIDDEN / 128, M_TOK / 128), 256>>>(
        p_lnh, p_lnl, w_fc1_h, w_fc1_l, fc1_b, nullptr,
        nullptr, p_f1h, p_f1l,
        nullptr, nullptr, nullptr, nullptr, nullptr, nullptr, M_TOK, HIDDEN, EMBED);
    // 7) out = x1 + fc1 @ fc2_w + fc2_b -> fp32
    bgemm_kernel<1><<<dim3(EMBED / 128, M_TOK / 128), 256>>>(
        p_f1h, p_f1l, w_fc2_h, w_fc2_l, fc2_b, p_x1,
        out, nullptr, nullptr,
        nullptr, nullptr, nullptr, nullptr, nullptr, nullptr, M_TOK, EMBED, HIDDEN);
}